// round 1
// baseline (speedup 1.0000x reference)
#include <cuda_runtime.h>
#include <cuda_bf16.h>
#include <math.h>

// Problem constants
#define BB   2048      // batch
#define TT   128       // time
#define DD   20        // input dim
#define HH   128       // hidden
#define G4   512       // 4*H
#define TM1  127       // T-1 steps
#define XT_ELEMS ((size_t)BB * TM1 * DD)   // X_tilde output elements

// Scratch: precomputed input-side gate contributions G_x[b][t][j]
__device__ float g_Gx[BB * TM1 * G4];      // 2048*127*512 floats = 532 MB (static device mem)

// ---------------------------------------------------------------------------
// Kernel 1: per-batch alpha = softmax(xw), X_tilde, and G_x = X_tilde@W_ih^T + b
// One block per batch. alpha is time-invariant (softmax shift-invariance).
// ---------------------------------------------------------------------------
__global__ __launch_bounds__(256) void prep_kernel(
    const float* __restrict__ X,       // [B][T][D]
    const float* __restrict__ W_attn,  // [1][2H+T]
    const float* __restrict__ W_ih,    // [4H][D]
    const float* __restrict__ b_ih,    // [4H]
    const float* __restrict__ b_hh,    // [4H]
    float* __restrict__ out)           // X_tilde region: [B][T-1][D]
{
    extern __shared__ float sm[];
    float* Xs   = sm;                  // [T*D]   = 2560
    float* Wih  = Xs + TT * DD;        // [512*21] padded stride 21 (conflict-free)
    float* bias = Wih + G4 * 21;       // [512]
    float* wxs  = bias + G4;           // [128]
    float* alpha = wxs + TT;           // [32]

    const int b = blockIdx.x;
    const int tid = threadIdx.x;
    const float* Xb = X + (size_t)b * TT * DD;

    for (int i = tid; i < TT * DD; i += 256) Xs[i] = Xb[i];
    for (int i = tid; i < TT; i += 256) wxs[i] = W_attn[2 * HH + i];
    for (int i = tid; i < G4; i += 256) bias[i] = b_ih[i] + b_hh[i];
    for (int i = tid; i < G4 * DD; i += 256) {
        int j = i / DD, d = i % DD;
        Wih[j * 21 + d] = W_ih[i];
    }
    __syncthreads();

    // xw[d] = sum_t X[t][d] * w_x[t]
    if (tid < DD) {
        float s = 0.f;
        for (int t = 0; t < TT; t++) s += Xs[t * DD + tid] * wxs[t];
        alpha[tid] = s;
    }
    __syncthreads();
    // softmax over D=20 (serial on thread 0 — tiny)
    if (tid == 0) {
        float mx = alpha[0];
        for (int d = 1; d < DD; d++) mx = fmaxf(mx, alpha[d]);
        float e[DD];
        float ssum = 0.f;
        for (int d = 0; d < DD; d++) { e[d] = expf(alpha[d] - mx); ssum += e[d]; }
        float inv = 1.f / ssum;
        for (int d = 0; d < DD; d++) alpha[d] = e[d] * inv;
    }
    __syncthreads();

    // X_tilde in smem (in place) + write to output region 1
    float* outXt = out + (size_t)b * TM1 * DD;
    for (int i = tid; i < TM1 * DD; i += 256) {
        int d = i % DD;
        float v = alpha[d] * Xs[i];
        Xs[i] = v;
        outXt[i] = v;
    }
    __syncthreads();

    // G_x[t][j] = bias[j] + sum_d X_tilde[t][d] * W_ih[j][d]
    float* Gxb = g_Gx + (size_t)b * TM1 * G4;
    for (int t = 0; t < TM1; t++) {
        float x[DD];
#pragma unroll
        for (int d = 0; d < DD; d++) x[d] = Xs[t * DD + d];   // broadcast LDS
#pragma unroll
        for (int j0 = 0; j0 < G4; j0 += 256) {
            int j = j0 + tid;
            float acc = bias[j];
#pragma unroll
            for (int d = 0; d < DD; d++) acc += x[d] * Wih[j * 21 + d];
            Gxb[t * G4 + j] = acc;
        }
    }
}

// ---------------------------------------------------------------------------
// Kernel 2: persistent per-batch-group LSTM recurrence.
// 128 blocks x 512 threads; each block owns 16 batches for all 127 steps.
// gates = G_x[t] + h @ W_hh^T, streamed W_hh through smem k-tiles (pure L2 hits).
// ---------------------------------------------------------------------------
#define NB   16        // batches per block
#define KT   64        // k-tile
#define WPAD 513       // Wt row pad (odd -> conflict-free compute reads)

__global__ __launch_bounds__(512, 1) void lstm_kernel(
    const float* __restrict__ W_hh,    // [4H][H] row-major
    float* __restrict__ out)           // full output buffer
{
    extern __shared__ float sm[];
    float* Wt = sm;                    // [KT][WPAD] = 64*513
    float* hs = Wt + KT * WPAD;        // [NB][128]
    float* cs = hs + NB * HH;          // [NB][128]
    float* gs = cs + NB * HH;          // [NB][512]

    const int tid = threadIdx.x;       // 0..511 == gate dim j
    const int b0 = blockIdx.x * NB;

    for (int i = tid; i < NB * HH; i += 512) { hs[i] = 0.f; cs[i] = 0.f; }

    const float* Gxp = g_Gx + (size_t)b0 * TM1 * G4;
    float* outE = out + XT_ELEMS;      // X_encoded region: [B][T-1][H]

    // W tile loader mapping: q = k-quad (0..15), rbase covers rows 0..511 in 16 passes
    const int q = tid & 15;
    const int rbase = tid >> 4;

    for (int t = 0; t < TM1; t++) {
        // input-side gate contribution for this step (long-latency loads, consumed late)
        float gx[NB];
#pragma unroll
        for (int bb = 0; bb < NB; bb++)
            gx[bb] = Gxp[(size_t)bb * TM1 * G4 + (size_t)t * G4 + tid];

        float acc[NB];
#pragma unroll
        for (int bb = 0; bb < NB; bb++) acc[bb] = 0.f;

        for (int kt = 0; kt < HH; kt += KT) {
            __syncthreads();   // prev-iter consumers of hs/Wt done
            // load Wt[k][j] = W_hh[j][kt+k], transposed, coalesced LDG.128
#pragma unroll
            for (int rr = 0; rr < 16; rr++) {
                int row = rbase + rr * 32;
                float4 w = *reinterpret_cast<const float4*>(&W_hh[row * HH + kt + q * 4]);
                Wt[(q * 4 + 0) * WPAD + row] = w.x;
                Wt[(q * 4 + 1) * WPAD + row] = w.y;
                Wt[(q * 4 + 2) * WPAD + row] = w.z;
                Wt[(q * 4 + 3) * WPAD + row] = w.w;
            }
            __syncthreads();

            // acc[bb] += sum_k W[j][k] * h[bb][k]
#pragma unroll 2
            for (int k = 0; k < KT; k += 4) {
                float w0 = Wt[(k + 0) * WPAD + tid];
                float w1 = Wt[(k + 1) * WPAD + tid];
                float w2 = Wt[(k + 2) * WPAD + tid];
                float w3 = Wt[(k + 3) * WPAD + tid];
#pragma unroll
                for (int bb = 0; bb < NB; bb++) {
                    float4 h4 = *reinterpret_cast<const float4*>(&hs[bb * HH + kt + k]);
                    acc[bb] = fmaf(w0, h4.x, acc[bb]);
                    acc[bb] = fmaf(w1, h4.y, acc[bb]);
                    acc[bb] = fmaf(w2, h4.z, acc[bb]);
                    acc[bb] = fmaf(w3, h4.w, acc[bb]);
                }
            }
        }

        // stage gates: gs[bb][j]
#pragma unroll
        for (int bb = 0; bb < NB; bb++) gs[bb * G4 + tid] = acc[bb] + gx[bb];
        __syncthreads();

        // LSTM cell update: 16*128 = 2048 (bb,m) pairs, 4 per thread
#pragma unroll
        for (int p = 0; p < 4; p++) {
            int idx = tid + 512 * p;       // 0..2047
            int bb = idx >> 7;
            int m = idx & (HH - 1);
            float i_ = gs[bb * G4 + m];
            float f_ = gs[bb * G4 + 128 + m];
            float g_ = gs[bb * G4 + 256 + m];
            float o_ = gs[bb * G4 + 384 + m];
            float si = 1.f / (1.f + expf(-i_));
            float sf = 1.f / (1.f + expf(-f_));
            float so = 1.f / (1.f + expf(-o_));
            float tg = tanhf(g_);
            float cn = sf * cs[idx] + si * tg;
            float hn = so * tanhf(cn);
            cs[idx] = cn;
            hs[idx] = hn;
            outE[((size_t)(b0 + bb) * TM1 + t) * HH + m] = hn;
        }
        // no trailing sync needed: next iteration's kt-loop syncs guard hs/gs reuse
    }
}

// ---------------------------------------------------------------------------
extern "C" void kernel_launch(void* const* d_in, const int* in_sizes, int n_in,
                              void* d_out, int out_size)
{
    const float* X      = (const float*)d_in[0];
    const float* W_attn = (const float*)d_in[1];
    // d_in[2] = b_attn: mathematically dead (softmax shift invariance)
    const float* W_ih   = (const float*)d_in[3];
    const float* W_hh   = (const float*)d_in[4];
    const float* b_ih   = (const float*)d_in[5];
    const float* b_hh   = (const float*)d_in[6];
    float* out = (float*)d_out;

    const int smem1 = (TT * DD + G4 * 21 + G4 + TT + 32) * 4;            // 55,936 B
    const int smem2 = (KT * WPAD + NB * HH * 2 + NB * G4) * 4;           // 180,480 B

    cudaFuncSetAttribute(prep_kernel, cudaFuncAttributeMaxDynamicSharedMemorySize, smem1);
    cudaFuncSetAttribute(lstm_kernel, cudaFuncAttributeMaxDynamicSharedMemorySize, smem2);

    prep_kernel<<<BB, 256, smem1>>>(X, W_attn, W_ih, b_ih, b_hh, out);
    lstm_kernel<<<BB / NB, 512, smem2>>>(W_hh, out);
}

// round 3
// speedup vs baseline: 1.6888x; 1.6888x over previous
#include <cuda_runtime.h>
#include <cuda_bf16.h>
#include <math.h>

// Problem constants
#define BB   2048      // batch
#define TT   128       // time
#define DD   20        // input dim
#define HH   128       // hidden
#define G4   512       // 4*H
#define TM1  127       // T-1 steps
#define XT_ELEMS ((size_t)BB * TM1 * DD)

// LSTM kernel tiling
#define NB    16       // batches per block
#define NTH   256      // threads (each owns gate rows tid and tid+256)
#define KS    88       // k-slices of W resident in smem
#define KR    40       // k-slices of W resident in registers (KS+KR=128)
#define HPAD  20       // hs row stride (k-major [k][bb], float4-aligned, low conflicts)
#define GPAD  18       // gs row stride ([j][bb], 8B-aligned for st.b64)

// Scratch: precomputed input-side gate contributions G_x[b][t][j]
__device__ float g_Gx[BB * TM1 * G4];

// ---------------------------------------------------------------------------
// fast transcendentals (error ~1e-6, threshold is 1e-3)
// ---------------------------------------------------------------------------
__device__ __forceinline__ float sigf(float x) {
    return __fdividef(1.f, 1.f + __expf(-x));
}
__device__ __forceinline__ float tanhfast(float x) {
    // tanh(x) = 2*sigmoid(2x) - 1
    return fmaf(2.f, __fdividef(1.f, 1.f + __expf(-2.f * x)), -1.f);
}

__device__ __forceinline__ unsigned long long pack2(float a, float b) {
    unsigned long long r;
    asm("mov.b64 %0, {%1, %2};" : "=l"(r) : "r"(__float_as_uint(a)), "r"(__float_as_uint(b)));
    return r;
}
__device__ __forceinline__ unsigned long long dup2(float a) {
    unsigned long long r;
    asm("mov.b64 %0, {%1, %1};" : "=l"(r) : "r"(__float_as_uint(a)));
    return r;
}
__device__ __forceinline__ void fma2(unsigned long long& d, unsigned long long a, unsigned long long b) {
    asm("fma.rn.f32x2 %0, %1, %2, %0;" : "+l"(d) : "l"(a), "l"(b));
}
__device__ __forceinline__ void lds128_u64x2(unsigned long long& a, unsigned long long& b, unsigned sa) {
    asm volatile("ld.shared.v2.u64 {%0, %1}, [%2];" : "=l"(a), "=l"(b) : "r"(sa));
}

// ---------------------------------------------------------------------------
// Kernel 1: alpha = softmax(xw) (time-invariant by softmax shift-invariance),
// X_tilde, and G_x = X_tilde@W_ih^T + b_ih + b_hh. One block per batch.
// ---------------------------------------------------------------------------
__global__ __launch_bounds__(256) void prep_kernel(
    const float* __restrict__ X,       // [B][T][D]
    const float* __restrict__ W_attn,  // [1][2H+T]
    const float* __restrict__ W_ih,    // [4H][D]
    const float* __restrict__ b_ih,    // [4H]
    const float* __restrict__ b_hh,    // [4H]
    float* __restrict__ out)           // X_tilde region: [B][T-1][D]
{
    extern __shared__ float sm[];
    float* Xs   = sm;                  // [T*D] = 2560
    float* Wih  = Xs + TT * DD;        // [512*21]
    float* bias = Wih + G4 * 21;       // [512]
    float* wxs  = bias + G4;           // [128]
    float* alpha = wxs + TT;           // [32]

    const int b = blockIdx.x;
    const int tid = threadIdx.x;
    const float* Xb = X + (size_t)b * TT * DD;

    for (int i = tid; i < TT * DD; i += 256) Xs[i] = Xb[i];
    for (int i = tid; i < TT; i += 256) wxs[i] = W_attn[2 * HH + i];
    for (int i = tid; i < G4; i += 256) bias[i] = b_ih[i] + b_hh[i];
    for (int i = tid; i < G4 * DD; i += 256) {
        int j = i / DD, d = i % DD;
        Wih[j * 21 + d] = W_ih[i];
    }
    __syncthreads();

    if (tid < DD) {
        float s = 0.f;
        for (int t = 0; t < TT; t++) s += Xs[t * DD + tid] * wxs[t];
        alpha[tid] = s;
    }
    __syncthreads();
    if (tid == 0) {
        float mx = alpha[0];
        for (int d = 1; d < DD; d++) mx = fmaxf(mx, alpha[d]);
        float e[DD];
        float ssum = 0.f;
        for (int d = 0; d < DD; d++) { e[d] = expf(alpha[d] - mx); ssum += e[d]; }
        float inv = 1.f / ssum;
        for (int d = 0; d < DD; d++) alpha[d] = e[d] * inv;
    }
    __syncthreads();

    float* outXt = out + (size_t)b * TM1 * DD;
    for (int i = tid; i < TM1 * DD; i += 256) {
        int d = i % DD;
        float v = alpha[d] * Xs[i];
        Xs[i] = v;
        outXt[i] = v;
    }
    __syncthreads();

    float* Gxb = g_Gx + (size_t)b * TM1 * G4;
    for (int t = 0; t < TM1; t++) {
        float x[DD];
#pragma unroll
        for (int d = 0; d < DD; d++) x[d] = Xs[t * DD + d];
#pragma unroll
        for (int j0 = 0; j0 < G4; j0 += 256) {
            int j = j0 + tid;
            float acc = bias[j];
#pragma unroll
            for (int d = 0; d < DD; d++) acc += x[d] * Wih[j * 21 + d];
            Gxb[t * G4 + j] = acc;
        }
    }
}

// ---------------------------------------------------------------------------
// Kernel 2: persistent LSTM recurrence, FFMA2-packed batch pairs.
// 128 blocks x 256 threads. Each thread owns gate rows j0=tid, j1=tid+256
// across 16 batches (8 packed pairs). W fully resident: 88 k in smem + 40 in regs.
// ---------------------------------------------------------------------------
__global__ __launch_bounds__(NTH, 1) void lstm_kernel(
    const float* __restrict__ W_hh,    // [4H][H] row-major
    float* __restrict__ out)
{
    extern __shared__ float sm[];
    float* Wlo = sm;                   // [KS][512]
    float* hs  = Wlo + KS * 512;       // [128][HPAD]  k-major h
    float* gs  = hs + 128 * HPAD;      // [512][GPAD]  gate staging [j][bb]

    const int tid = threadIdx.x;
    const int b0 = blockIdx.x * NB;

    // ---- prologue: load W ----
    for (int idx = tid; idx < 512 * 128; idx += NTH) {
        int j = idx >> 7, k = idx & 127;
        if (k < KS) Wlo[k * 512 + j] = W_hh[idx];
    }
    float wreg[2][KR];
#pragma unroll
    for (int jj = 0; jj < 2; jj++) {
        const float4* wp = reinterpret_cast<const float4*>(&W_hh[(tid + 256 * jj) * HH + KS]);
#pragma unroll
        for (int r4 = 0; r4 < KR / 4; r4++) {
            float4 w = wp[r4];
            wreg[jj][4 * r4 + 0] = w.x;
            wreg[jj][4 * r4 + 1] = w.y;
            wreg[jj][4 * r4 + 2] = w.z;
            wreg[jj][4 * r4 + 3] = w.w;
        }
    }
    for (int i = tid; i < 128 * HPAD; i += NTH) hs[i] = 0.f;
    float creg[8];
#pragma unroll
    for (int p = 0; p < 8; p++) creg[p] = 0.f;
    __syncthreads();

    const float* Gxp = g_Gx + (size_t)b0 * TM1 * G4;
    float* outE = out + XT_ELEMS;

    const unsigned hs_sa = (unsigned)__cvta_generic_to_shared(hs);

    for (int t = 0; t < TM1; t++) {
        // ---- acc init = packed G_x (loads issued early, hidden under GEMM) ----
        unsigned long long acc[2][8];
#pragma unroll
        for (int jj = 0; jj < 2; jj++) {
            const float* gp = Gxp + (size_t)t * G4 + (tid + 256 * jj);
#pragma unroll
            for (int p = 0; p < 8; p++) {
                float glo = gp[(size_t)(2 * p)     * TM1 * G4];
                float ghi = gp[(size_t)(2 * p + 1) * TM1 * G4];
                acc[jj][p] = pack2(glo, ghi);
            }
        }

        // ---- GEMM: gates[j][bb] += sum_k W[j][k] * h[k][bb], packed pairs ----
#pragma unroll 8
        for (int k = 0; k < KS; k++) {
            unsigned long long w0 = dup2(Wlo[k * 512 + tid]);
            unsigned long long w1 = dup2(Wlo[k * 512 + tid + 256]);
            unsigned long long h0, h1, h2, h3, h4, h5, h6, h7;
            unsigned sa = hs_sa + (unsigned)(k * HPAD * 4);
            lds128_u64x2(h0, h1, sa);
            lds128_u64x2(h2, h3, sa + 16);
            lds128_u64x2(h4, h5, sa + 32);
            lds128_u64x2(h6, h7, sa + 48);
            fma2(acc[0][0], w0, h0); fma2(acc[1][0], w1, h0);
            fma2(acc[0][1], w0, h1); fma2(acc[1][1], w1, h1);
            fma2(acc[0][2], w0, h2); fma2(acc[1][2], w1, h2);
            fma2(acc[0][3], w0, h3); fma2(acc[1][3], w1, h3);
            fma2(acc[0][4], w0, h4); fma2(acc[1][4], w1, h4);
            fma2(acc[0][5], w0, h5); fma2(acc[1][5], w1, h5);
            fma2(acc[0][6], w0, h6); fma2(acc[1][6], w1, h6);
            fma2(acc[0][7], w0, h7); fma2(acc[1][7], w1, h7);
        }
#pragma unroll
        for (int r = 0; r < KR; r++) {
            int k = KS + r;
            unsigned long long w0 = dup2(wreg[0][r]);
            unsigned long long w1 = dup2(wreg[1][r]);
            unsigned long long h0, h1, h2, h3, h4, h5, h6, h7;
            unsigned sa = hs_sa + (unsigned)(k * HPAD * 4);
            lds128_u64x2(h0, h1, sa);
            lds128_u64x2(h2, h3, sa + 16);
            lds128_u64x2(h4, h5, sa + 32);
            lds128_u64x2(h6, h7, sa + 48);
            fma2(acc[0][0], w0, h0); fma2(acc[1][0], w1, h0);
            fma2(acc[0][1], w0, h1); fma2(acc[1][1], w1, h1);
            fma2(acc[0][2], w0, h2); fma2(acc[1][2], w1, h2);
            fma2(acc[0][3], w0, h3); fma2(acc[1][3], w1, h3);
            fma2(acc[0][4], w0, h4); fma2(acc[1][4], w1, h4);
            fma2(acc[0][5], w0, h5); fma2(acc[1][5], w1, h5);
            fma2(acc[0][6], w0, h6); fma2(acc[1][6], w1, h6);
            fma2(acc[0][7], w0, h7); fma2(acc[1][7], w1, h7);
        }

        // ---- stage gates gs[j][bb] (st.b64, 8B aligned: GPAD even) ----
#pragma unroll
        for (int jj = 0; jj < 2; jj++) {
            float* gp = gs + (tid + 256 * jj) * GPAD;
#pragma unroll
            for (int p = 0; p < 8; p++) {
                *reinterpret_cast<unsigned long long*>(gp + 2 * p) = acc[jj][p];
            }
        }
        __syncthreads();

        // ---- LSTM cell: 2048 elements, 8 per thread; c in registers ----
#pragma unroll
        for (int p = 0; p < 8; p++) {
            int idx = tid + NTH * p;        // 0..2047
            int bb = idx >> 7;
            int m = idx & (HH - 1);
            float i_ = gs[(m      ) * GPAD + bb];
            float f_ = gs[(m + 128) * GPAD + bb];
            float g_ = gs[(m + 256) * GPAD + bb];
            float o_ = gs[(m + 384) * GPAD + bb];
            float si = sigf(i_);
            float sf = sigf(f_);
            float so = sigf(o_);
            float tg = tanhfast(g_);
            float cn = fmaf(sf, creg[p], si * tg);
            float hn = so * tanhfast(cn);
            creg[p] = cn;
            hs[m * HPAD + bb] = hn;
            outE[((size_t)(b0 + bb) * TM1 + t) * HH + m] = hn;
        }
        __syncthreads();   // hs complete before next step's GEMM reads
    }
}

// ---------------------------------------------------------------------------
extern "C" void kernel_launch(void* const* d_in, const int* in_sizes, int n_in,
                              void* d_out, int out_size)
{
    const float* X      = (const float*)d_in[0];
    const float* W_attn = (const float*)d_in[1];
    // d_in[2] = b_attn: dead (softmax shift invariance)
    const float* W_ih   = (const float*)d_in[3];
    const float* W_hh   = (const float*)d_in[4];
    const float* b_ih   = (const float*)d_in[5];
    const float* b_hh   = (const float*)d_in[6];
    float* out = (float*)d_out;

    const int smem1 = (TT * DD + G4 * 21 + G4 + TT + 32) * 4;           // 55,936 B
    const int smem2 = (KS * 512 + 128 * HPAD + G4 * GPAD) * 4;          // 227,328 B

    cudaFuncSetAttribute(prep_kernel, cudaFuncAttributeMaxDynamicSharedMemorySize, smem1);
    cudaFuncSetAttribute(lstm_kernel, cudaFuncAttributeMaxDynamicSharedMemorySize, smem2);

    prep_kernel<<<BB, 256, smem1>>>(X, W_attn, W_ih, b_ih, b_hh, out);
    lstm_kernel<<<BB / NB, NTH, smem2>>>(W_hh, out);
}

// round 5
// speedup vs baseline: 1.6950x; 1.0037x over previous
#include <cuda_runtime.h>
#include <cuda_bf16.h>
#include <math.h>

// Problem constants
#define BB   2048      // batch
#define TT   128       // time
#define DD   20        // input dim
#define HH   128       // hidden
#define G4   512       // 4*H
#define TM1  127       // T-1 steps
#define XT_ELEMS ((size_t)BB * TM1 * DD)

// LSTM kernel tiling
#define NB    16       // batches per block
#define NTH   256      // threads (each owns gate rows tid and tid+256)
#define KS    88       // k-slices of W resident in smem
#define KR    40       // k-slices of W resident in registers (KS+KR=128)
#define HPAD  20       // hs row stride (k-major [k][bb]; mult of 4 for 16B loads)
#define GPAD  18       // gs row stride ([j][bb], even for u64 stores)

// Scratch: precomputed input-side gate contributions, PAIR-INTERLEAVED:
// element (b, t, j) lives at g_Gx[ ((b>>1)*TM1*G4)*2 + (t*G4 + j)*2 + (b&1) ]
// so batches (2q, 2q+1) for the same (t,j) are adjacent -> one LDG.64 per pair.
__device__ float g_Gx[BB * TM1 * G4];

// ---------------------------------------------------------------------------
// fast transcendentals (error ~1e-6, threshold is 1e-3)
// ---------------------------------------------------------------------------
__device__ __forceinline__ float sigf(float x) {
    return __fdividef(1.f, 1.f + __expf(-x));
}
__device__ __forceinline__ float tanhfast(float x) {
    return fmaf(2.f, __fdividef(1.f, 1.f + __expf(-2.f * x)), -1.f);
}

__device__ __forceinline__ unsigned long long dup2(float a) {
    unsigned long long r;
    asm("mov.b64 %0, {%1, %1};" : "=l"(r) : "r"(__float_as_uint(a)));
    return r;
}
__device__ __forceinline__ void fma2(unsigned long long& d, unsigned long long a, unsigned long long b) {
    asm("fma.rn.f32x2 %0, %1, %2, %0;" : "+l"(d) : "l"(a), "l"(b));
}

// ---------------------------------------------------------------------------
// Kernel 1: alpha = softmax(xw) (time-invariant by softmax shift-invariance),
// X_tilde, and G_x = X_tilde@W_ih^T + b_ih + b_hh. One block per batch.
// ---------------------------------------------------------------------------
__global__ __launch_bounds__(256) void prep_kernel(
    const float* __restrict__ X,       // [B][T][D]
    const float* __restrict__ W_attn,  // [1][2H+T]
    const float* __restrict__ W_ih,    // [4H][D]
    const float* __restrict__ b_ih,    // [4H]
    const float* __restrict__ b_hh,    // [4H]
    float* __restrict__ out)           // X_tilde region: [B][T-1][D]
{
    extern __shared__ float sm[];
    float* Xs   = sm;                  // [T*D] = 2560
    float* Wih  = Xs + TT * DD;        // [512*21]
    float* bias = Wih + G4 * 21;       // [512]
    float* wxs  = bias + G4;           // [128]
    float* alpha = wxs + TT;           // [32]

    const int b = blockIdx.x;
    const int tid = threadIdx.x;
    const float* Xb = X + (size_t)b * TT * DD;

    for (int i = tid; i < TT * DD; i += 256) Xs[i] = Xb[i];
    for (int i = tid; i < TT; i += 256) wxs[i] = W_attn[2 * HH + i];
    for (int i = tid; i < G4; i += 256) bias[i] = b_ih[i] + b_hh[i];
    for (int i = tid; i < G4 * DD; i += 256) {
        int j = i / DD, d = i % DD;
        Wih[j * 21 + d] = W_ih[i];
    }
    __syncthreads();

    if (tid < DD) {
        float s = 0.f;
        for (int t = 0; t < TT; t++) s += Xs[t * DD + tid] * wxs[t];
        alpha[tid] = s;
    }
    __syncthreads();
    if (tid == 0) {
        float mx = alpha[0];
        for (int d = 1; d < DD; d++) mx = fmaxf(mx, alpha[d]);
        float e[DD];
        float ssum = 0.f;
        for (int d = 0; d < DD; d++) { e[d] = expf(alpha[d] - mx); ssum += e[d]; }
        float inv = 1.f / ssum;
        for (int d = 0; d < DD; d++) alpha[d] = e[d] * inv;
    }
    __syncthreads();

    float* outXt = out + (size_t)b * TM1 * DD;
    for (int i = tid; i < TM1 * DD; i += 256) {
        int d = i % DD;
        float v = alpha[d] * Xs[i];
        Xs[i] = v;
        outXt[i] = v;
    }
    __syncthreads();

    // pair-interleaved G_x write
    float* Gxb = g_Gx + ((size_t)(b >> 1) * TM1 * G4) * 2 + (b & 1);
    for (int t = 0; t < TM1; t++) {
        float x[DD];
#pragma unroll
        for (int d = 0; d < DD; d++) x[d] = Xs[t * DD + d];
#pragma unroll
        for (int j0 = 0; j0 < G4; j0 += 256) {
            int j = j0 + tid;
            float acc = bias[j];
#pragma unroll
            for (int d = 0; d < DD; d++) acc += x[d] * Wih[j * 21 + d];
            Gxb[((size_t)t * G4 + j) * 2] = acc;
        }
    }
}

// ---------------------------------------------------------------------------
// Kernel 2: persistent LSTM recurrence, FFMA2-packed batch pairs.
// 128 blocks x 256 threads. Each thread owns gate rows j0=tid, j1=tid+256
// across 16 batches (8 packed pairs). W fully resident: 88 k in smem + 40 in regs.
// G_x for step t+1 is prefetched into registers during step t's GEMM.
// ---------------------------------------------------------------------------
__global__ __launch_bounds__(NTH, 1) void lstm_kernel(
    const float* __restrict__ W_hh,    // [4H][H] row-major
    float* __restrict__ out)
{
    extern __shared__ float sm[];
    float* Wlo = sm;                   // [KS][512]  k-major W
    float* hs  = Wlo + KS * 512;       // [128][HPAD]  k-major h
    float* gs  = hs + 128 * HPAD;      // [512][GPAD]  gate staging [j][bb]

    const int tid = threadIdx.x;
    const int b0 = blockIdx.x * NB;

    // ---- prologue: load W ----
    for (int idx = tid; idx < 512 * 128; idx += NTH) {
        int j = idx >> 7, k = idx & 127;
        if (k < KS) Wlo[k * 512 + j] = W_hh[idx];
    }
    float wreg[2][KR];
#pragma unroll
    for (int jj = 0; jj < 2; jj++) {
        const float4* wp = reinterpret_cast<const float4*>(&W_hh[(tid + 256 * jj) * HH + KS]);
#pragma unroll
        for (int r4 = 0; r4 < KR / 4; r4++) {
            float4 w = wp[r4];
            wreg[jj][4 * r4 + 0] = w.x;
            wreg[jj][4 * r4 + 1] = w.y;
            wreg[jj][4 * r4 + 2] = w.z;
            wreg[jj][4 * r4 + 3] = w.w;
        }
    }
    for (int i = tid; i < 128 * HPAD; i += NTH) hs[i] = 0.f;
    float creg[8];
#pragma unroll
    for (int p = 0; p < 8; p++) creg[p] = 0.f;
    __syncthreads();

    // G_x base (pair-interleaved layout)
    const int q0 = blockIdx.x * (NB / 2);   // first batch-pair index
    const unsigned long long* Gx64 = reinterpret_cast<const unsigned long long*>(g_Gx);
    // element for (pair q0+p, t, j): Gx64[ (q0+p)*TM1*G4 + t*G4 + j ]

    float* outE = out + XT_ELEMS;

    // prefetch G_x for t=0
    unsigned long long gxb[2][8];
#pragma unroll
    for (int jj = 0; jj < 2; jj++) {
        int j = tid + 256 * jj;
#pragma unroll
        for (int p = 0; p < 8; p++)
            gxb[jj][p] = Gx64[(size_t)(q0 + p) * TM1 * G4 + j];
    }

    const int m_cell = tid & (HH - 1);
    const int bb0_cell = tid >> 7;

    for (int t = 0; t < TM1; t++) {
        // ---- acc init from prefetched G_x ----
        unsigned long long acc[2][8];
#pragma unroll
        for (int jj = 0; jj < 2; jj++)
#pragma unroll
            for (int p = 0; p < 8; p++) acc[jj][p] = gxb[jj][p];

        // ---- issue next step's G_x loads (hidden under GEMM) ----
        if (t + 1 < TM1) {
#pragma unroll
            for (int jj = 0; jj < 2; jj++) {
                int j = tid + 256 * jj;
#pragma unroll
                for (int p = 0; p < 8; p++)
                    gxb[jj][p] = Gx64[(size_t)(q0 + p) * TM1 * G4 + (size_t)(t + 1) * G4 + j];
            }
        }

        // ---- GEMM: gates[j][bb] += sum_k W[j][k] * h[k][bb], packed pairs ----
#pragma unroll 4
        for (int k = 0; k < KS; k++) {
            unsigned long long w0 = dup2(Wlo[k * 512 + tid]);
            unsigned long long w1 = dup2(Wlo[k * 512 + tid + 256]);
            const ulonglong2* hp = reinterpret_cast<const ulonglong2*>(hs + k * HPAD);
            ulonglong2 ha = hp[0];
            ulonglong2 hb = hp[1];
            ulonglong2 hc = hp[2];
            ulonglong2 hd = hp[3];
            fma2(acc[0][0], w0, ha.x); fma2(acc[1][0], w1, ha.x);
            fma2(acc[0][1], w0, ha.y); fma2(acc[1][1], w1, ha.y);
            fma2(acc[0][2], w0, hb.x); fma2(acc[1][2], w1, hb.x);
            fma2(acc[0][3], w0, hb.y); fma2(acc[1][3], w1, hb.y);
            fma2(acc[0][4], w0, hc.x); fma2(acc[1][4], w1, hc.x);
            fma2(acc[0][5], w0, hc.y); fma2(acc[1][5], w1, hc.y);
            fma2(acc[0][6], w0, hd.x); fma2(acc[1][6], w1, hd.x);
            fma2(acc[0][7], w0, hd.y); fma2(acc[1][7], w1, hd.y);
        }
#pragma unroll
        for (int r = 0; r < KR; r++) {
            int k = KS + r;
            unsigned long long w0 = dup2(wreg[0][r]);
            unsigned long long w1 = dup2(wreg[1][r]);
            const ulonglong2* hp = reinterpret_cast<const ulonglong2*>(hs + k * HPAD);
            ulonglong2 ha = hp[0];
            ulonglong2 hb = hp[1];
            ulonglong2 hc = hp[2];
            ulonglong2 hd = hp[3];
            fma2(acc[0][0], w0, ha.x); fma2(acc[1][0], w1, ha.x);
            fma2(acc[0][1], w0, ha.y); fma2(acc[1][1], w1, ha.y);
            fma2(acc[0][2], w0, hb.x); fma2(acc[1][2], w1, hb.x);
            fma2(acc[0][3], w0, hb.y); fma2(acc[1][3], w1, hb.y);
            fma2(acc[0][4], w0, hc.x); fma2(acc[1][4], w1, hc.x);
            fma2(acc[0][5], w0, hc.y); fma2(acc[1][5], w1, hc.y);
            fma2(acc[0][6], w0, hd.x); fma2(acc[1][6], w1, hd.x);
            fma2(acc[0][7], w0, hd.y); fma2(acc[1][7], w1, hd.y);
        }

        // ---- stage gates gs[j][bb] (u64 stores, 8B aligned) ----
#pragma unroll
        for (int jj = 0; jj < 2; jj++) {
            float* gp = gs + (tid + 256 * jj) * GPAD;
#pragma unroll
            for (int p = 0; p < 8; p++)
                *reinterpret_cast<unsigned long long*>(gp + 2 * p) = acc[jj][p];
        }
        __syncthreads();

        // ---- LSTM cell: each thread owns one m, 8 batches ----
#pragma unroll
        for (int p = 0; p < 8; p++) {
            int bb = bb0_cell + 2 * p;
            float i_ = gs[(m_cell      ) * GPAD + bb];
            float f_ = gs[(m_cell + 128) * GPAD + bb];
            float g_ = gs[(m_cell + 256) * GPAD + bb];
            float o_ = gs[(m_cell + 384) * GPAD + bb];
            float si = sigf(i_);
            float sf = sigf(f_);
            float so = sigf(o_);
            float tg = tanhfast(g_);
            float cn = fmaf(sf, creg[p], si * tg);
            float hn = so * tanhfast(cn);
            creg[p] = cn;
            hs[m_cell * HPAD + bb] = hn;
            outE[((size_t)(b0 + bb) * TM1 + t) * HH + m_cell] = hn;
        }
        __syncthreads();   // hs complete before next step's GEMM reads
    }
}

// ---------------------------------------------------------------------------
extern "C" void kernel_launch(void* const* d_in, const int* in_sizes, int n_in,
                              void* d_out, int out_size)
{
    const float* X      = (const float*)d_in[0];
    const float* W_attn = (const float*)d_in[1];
    // d_in[2] = b_attn: dead (softmax shift invariance)
    const float* W_ih   = (const float*)d_in[3];
    const float* W_hh   = (const float*)d_in[4];
    const float* b_ih   = (const float*)d_in[5];
    const float* b_hh   = (const float*)d_in[6];
    float* out = (float*)d_out;

    const int smem1 = (TT * DD + G4 * 21 + G4 + TT + 32) * 4;           // 55,936 B
    const int smem2 = (KS * 512 + 128 * HPAD + G4 * GPAD) * 4;          // 227,328 B

    cudaFuncSetAttribute(prep_kernel, cudaFuncAttributeMaxDynamicSharedMemorySize, smem1);
    cudaFuncSetAttribute(lstm_kernel, cudaFuncAttributeMaxDynamicSharedMemorySize, smem2);

    prep_kernel<<<BB, 256, smem1>>>(X, W_attn, W_ih, b_ih, b_hh, out);
    lstm_kernel<<<BB / NB, NTH, smem2>>>(W_hh, out);
}